// round 17
// baseline (speedup 1.0000x reference)
#include <cuda_runtime.h>
#include <cuda_bf16.h>
#include <cstdint>

// Retrace loss — persistent CTAs, HYBRID staging:
//   * eQ,tQ,tp,bp: 3-deep TMA (cp.async.bulk 1D) pipeline into smem stages
//   * Q,r:         2-deep scalar register prefetch + warp-private smem transpose
// grid = 592 = 148 SM * 4 CTA (single wave). row*1025 ≡ bid (mod 4) => window
// residue c = bid&3 constant per CTA; staged arrays read at word offset c+2 via
// <=2 conflict-free LDS.128 + uniform selects.
// Scan per row: serial compose 4 -> one warp suffix scan -> cross-warp combine
// (double-buffered totals, ONE __syncthreads, redundant per-thread compose).
// Completion: one arrival per CTA; wrap-around counter -> deterministic replays.
// Affine composition: (A1,B1) o (A2,B2) = (A1 + B1*A2, B1*B2).

#define S_STRIDE 1025
#define T_LEN    1024
#define NROWS    4096
#define GAMMA_F  0.99f
#define EPS_F    1e-10f
#define NTHREADS 256
#define GRID     592

#define NARR_T          4                      // TMA-staged arrays
#define NSTAGE          3
#define SEG_COPY_BYTES  4112                   // 1028 words, mult of 16
#define SEG_ALLOC_WORDS 1032                   // pads the hi-chunk overread
#define STAGE_WORDS     (NARR_T * SEG_ALLOC_WORDS)
#define SMEM_BYTES      (NSTAGE * STAGE_WORDS * 4)   // 49536 B dynamic

__device__ double   g_part[GRID];
__device__ unsigned g_cnt = 0;   // wraps at GRID-1 -> deterministic across replays

struct Aff { float a, b; };

__device__ __forceinline__ Aff comp(Aff f, Aff g) {
    Aff r;
    r.a = fmaf(f.b, g.a, f.a);
    r.b = f.b * g.b;
    return r;
}

__device__ __forceinline__ uint32_t smem_u32(const void* p) {
    return (uint32_t)__cvta_generic_to_shared(p);
}
__device__ __forceinline__ void mbar_init(uint32_t bar, uint32_t cnt) {
    asm volatile("mbarrier.init.shared.b64 [%0], %1;" :: "r"(bar), "r"(cnt) : "memory");
}
__device__ __forceinline__ void mbar_expect_tx(uint32_t bar, uint32_t bytes) {
    asm volatile("mbarrier.arrive.expect_tx.shared.b64 _, [%0], %1;"
                 :: "r"(bar), "r"(bytes) : "memory");
}
__device__ __forceinline__ void mbar_wait(uint32_t bar, uint32_t parity) {
    asm volatile(
        "{\n\t"
        ".reg .pred P1;\n\t"
        "WAIT_LOOP_%=:\n\t"
        "mbarrier.try_wait.parity.acquire.cta.shared::cta.b64 P1, [%0], %1, 0x989680;\n\t"
        "@P1 bra.uni WAIT_DONE_%=;\n\t"
        "bra.uni WAIT_LOOP_%=;\n\t"
        "WAIT_DONE_%=:\n\t"
        "}"
        :: "r"(bar), "r"(parity) : "memory");
}
__device__ __forceinline__ void bulk_copy(uint32_t dst_smem, const float* src,
                                          uint32_t bytes, uint32_t bar) {
    asm volatile(
        "cp.async.bulk.shared::cta.global.mbarrier::complete_tx::bytes [%0], [%1], %2, [%3];"
        :: "r"(dst_smem), "l"(src), "r"(bytes), "r"(bar) : "memory");
}

// Read words off+j0 .. +3 from a staged array (off = c+2 uniform per CTA).
__device__ __forceinline__ float4 lds_shift(const float* arr, int off, int j0) {
    const float4* p = reinterpret_cast<const float4*>(arr);
    const int q0 = (off + j0) >> 2;      // j0 mult of 4
    const int m  = off & 3;
    const float4 lo = p[q0];             // 16B/lane stride: conflict-free
    if (m == 0) return lo;
    const float4 hi = p[q0 + 1];
    float4 o;
    if (m == 1)      { o.x = lo.y; o.y = lo.z; o.z = lo.w; o.w = hi.x; }
    else if (m == 2) { o.x = lo.z; o.y = lo.w; o.z = hi.x; o.w = hi.y; }
    else             { o.x = lo.w; o.y = hi.x; o.z = hi.y; o.w = hi.z; }
    return o;
}

struct QR { float qv[4], rv[4], init; };   // 9-reg scalar prefetch

__device__ __forceinline__ void load_qr(QR& R, long base, int seg, int lane,
                                        const float* __restrict__ Q,
                                        const float* __restrict__ r)
{
#pragma unroll
    for (int p = 0; p < 4; p++) {
        const int i = seg + p * 32 + lane;
        R.qv[p] = __ldcs(&Q[base + i]);
        R.rv[p] = __ldcs(&r[base + i + 1]);
    }
    R.init = __ldcs(&Q[base + T_LEN]);
}

__global__ void __launch_bounds__(NTHREADS, 4)
retrace_kernel(const float* __restrict__ Q,
               const float* __restrict__ eQ,
               const float* __restrict__ tQ,
               const float* __restrict__ r,
               const float* __restrict__ tp,
               const float* __restrict__ bp,
               float* __restrict__ out)
{
    extern __shared__ __align__(16) float smem[];       // TMA stages
    __shared__ __align__(16) float sT[8][128];          // Q/r transpose (reused)
    __shared__ __align__(8) unsigned long long mbar[NSTAGE];
    __shared__ float swA[2][8], swB[2][8];
    __shared__ double ssum[8];
    __shared__ bool s_last;

    const int bid = blockIdx.x;
    const int t = threadIdx.x;
    const int lane = t & 31;
    const int w = t >> 5;
    const int seg = w * 128;
    const int j0 = seg + 4 * lane;
    const int c = bid & 3;

    const float* arrs[NARR_T] = { eQ, tQ, tp, bp };
    const uint32_t smem_base = smem_u32(smem);
    uint32_t bar_u[NSTAGE];
#pragma unroll
    for (int s = 0; s < NSTAGE; s++) bar_u[s] = smem_u32(&mbar[s]);

    if (t == 0) {
#pragma unroll
        for (int s = 0; s < NSTAGE; s++) mbar_init(bar_u[s], 1);
    }
    __syncthreads();

    auto issue = [&](int row, int stage) {
        const long astart = (long)row * S_STRIDE - c;   // 16B-aligned
        mbar_expect_tx(bar_u[stage], NARR_T * SEG_COPY_BYTES);
#pragma unroll
        for (int a = 0; a < NARR_T; a++) {
            const uint32_t dst = smem_base + (uint32_t)(stage * STAGE_WORDS
                                                        + a * SEG_ALLOC_WORDS) * 4u;
            bulk_copy(dst, arrs[a] + astart, SEG_COPY_BYTES, bar_u[stage]);
        }
    };

    if (t == 0) {
        issue(bid, 0);
        if (bid + GRID < NROWS) issue(bid + GRID, 1);
        if (bid + 2 * GRID < NROWS) issue(bid + 2 * GRID, 2);
    }

    QR R;
    load_qr(R, (long)bid * S_STRIDE, seg, lane, Q, r);

    double acc = 0.0;
    int ph[NSTAGE] = { 0, 0, 0 };
    int st = 0, buf = 0;
    int row = bid;

    while (row < NROWS) {
        const int next = row + GRID;

        // ---- transpose Q then r through the warp-private buffer
        float q4x, q4y, q4z, q4w, r4x, r4y, r4z, r4w;
        {
            __syncwarp();
#pragma unroll
            for (int p = 0; p < 4; p++) sT[w][p * 32 + lane] = R.qv[p];
            __syncwarp();
            const float4 v = reinterpret_cast<const float4*>(sT[w])[lane];
            q4x = v.x; q4y = v.y; q4z = v.z; q4w = v.w;
            __syncwarp();
#pragma unroll
            for (int p = 0; p < 4; p++) sT[w][p * 32 + lane] = R.rv[p];
            __syncwarp();
            const float4 v2 = reinterpret_cast<const float4*>(sT[w])[lane];
            r4x = v2.x; r4y = v2.y; r4z = v2.z; r4w = v2.w;
        }
        const float initv = R.init;

        // ---- issue next row's scalar loads; they fly during wait+scan
        if (next < NROWS)
            load_qr(R, (long)next * S_STRIDE, seg, lane, Q, r);

        // ---- wait for this row's TMA stage, then consume
        mbar_wait(bar_u[st], ph[st]);
        ph[st] ^= 1;

        const float* S0 = smem + st * STAGE_WORDS;
        const float4 ev = lds_shift(S0,                       c + 2, j0);
        const float4 tq = lds_shift(S0 + 1 * SEG_ALLOC_WORDS, c + 2, j0);
        const float4 pt = lds_shift(S0 + 2 * SEG_ALLOC_WORDS, c + 2, j0);
        const float4 pb = lds_shift(S0 + 3 * SEG_ALLOC_WORDS, c + 2, j0);

        // build affine maps (identity for j==1023)
        const float PT[4] = {pt.x, pt.y, pt.z, pt.w};
        const float PB[4] = {pb.x, pb.y, pb.z, pb.w};
        const float RV[4] = {r4x, r4y, r4z, r4w};
        const float EV[4] = {ev.x, ev.y, ev.z, ev.w};
        const float TQ[4] = {tq.x, tq.y, tq.z, tq.w};
        const float QV[4] = {q4x, q4y, q4z, q4w};
        Aff loc[4];
#pragma unroll
        for (int k = 0; k < 4; k++) {
            if (j0 + k < T_LEN - 1) {
                const float cc = fminf(fmaxf(__fdividef(PT[k], PB[k]), EPS_F), 1.0f);
                loc[k].b = GAMMA_F * cc;
                loc[k].a = fmaf(GAMMA_F, EV[k], RV[k]) - loc[k].b * TQ[k];
            } else {
                loc[k].a = 0.0f; loc[k].b = 1.0f;
            }
        }

        // serial suffix composition within thread
        Aff suf[4];
        suf[3] = loc[3];
#pragma unroll
        for (int k = 2; k >= 0; k--) suf[k] = comp(loc[k], suf[k + 1]);

        // one warp-level inclusive suffix scan of thread aggregates
        Aff v = suf[0];
#pragma unroll
        for (int off = 1; off < 32; off <<= 1) {
            const float oa = __shfl_down_sync(0xffffffffu, v.a, off);
            const float ob = __shfl_down_sync(0xffffffffu, v.b, off);
            if (lane + off < 32) { Aff g; g.a = oa; g.b = ob; v = comp(v, g); }
        }

        // in-warp EXCLUSIVE suffix
        const float ea = __shfl_down_sync(0xffffffffu, v.a, 1);
        const float eb = __shfl_down_sync(0xffffffffu, v.b, 1);
        Aff inwexcl;
        if (lane == 31) { inwexcl.a = 0.0f; inwexcl.b = 1.0f; }
        else            { inwexcl.a = ea;   inwexcl.b = eb;   }

        // publish warp totals (double-buffered), ONE barrier
        if (lane == 0) { swA[buf][w] = v.a; swB[buf][w] = v.b; }
        __syncthreads();

        // stage fully consumed -> refill for row + 3*GRID (overlaps epilogue)
        if (t == 0 && row + NSTAGE * GRID < NROWS) issue(row + NSTAGE * GRID, st);

        // redundant per-thread composition of later warps
        Aff W; W.a = 0.0f; W.b = 1.0f;
        for (int ww = 7; ww > w; ww--) {
            Aff tot; tot.a = swA[buf][ww]; tot.b = swB[buf][ww];
            W = comp(tot, W);
        }
        const Aff S = comp(inwexcl, W);

        // epilogue
        float fsum = 0.0f;
#pragma unroll
        for (int k = 0; k < 4; k++) {
            const Aff m = comp(suf[k], S);
            const float y = fmaf(m.b, initv, m.a);
            const float d = QV[k] - y;
            fsum = fmaf(d, d, fsum);
        }
        acc += (double)fsum;

        buf ^= 1;
        st = (st + 1 == NSTAGE) ? 0 : st + 1;
        row = next;
    }

    // ---- final: block-reduce per-thread doubles, one arrival per CTA
#pragma unroll
    for (int off = 16; off > 0; off >>= 1)
        acc += __shfl_down_sync(0xffffffffu, acc, off);
    if (lane == 0) ssum[w] = acc;
    __syncthreads();

    if (t == 0) {
        double x = 0.0;
#pragma unroll
        for (int i = 0; i < 8; i++) x += ssum[i];
        __stcg(&g_part[bid], x);
        __threadfence();
        const unsigned old = atomicInc(&g_cnt, GRID - 1);
        s_last = (old == GRID - 1);
    }
    __syncthreads();

    if (s_last) {
        double x = 0.0;
        for (int i = t; i < GRID; i += NTHREADS)
            x += __ldcg(&g_part[i]);
#pragma unroll
        for (int off = 16; off > 0; off >>= 1)
            x += __shfl_down_sync(0xffffffffu, x, off);
        __shared__ double fs2[8];
        if (lane == 0) fs2[w] = x;
        __syncthreads();
        if (t == 0) {
            double tot = 0.0;
#pragma unroll
            for (int i = 0; i < 8; i++) tot += fs2[i];
            out[0] = (float)(tot / (double)((long long)NROWS * T_LEN));
        }
    }
}

extern "C" void kernel_launch(void* const* d_in, const int* in_sizes, int n_in,
                              void* d_out, int out_size)
{
    const float* Q   = (const float*)d_in[0];
    const float* eQ  = (const float*)d_in[1];
    const float* tQ  = (const float*)d_in[2];
    const float* r   = (const float*)d_in[3];
    const float* tp  = (const float*)d_in[4];
    const float* bp  = (const float*)d_in[5];
    float* out = (float*)d_out;

    static bool attr_set = false;
    if (!attr_set) {
        cudaFuncSetAttribute(retrace_kernel,
                             cudaFuncAttributeMaxDynamicSharedMemorySize, SMEM_BYTES);
        attr_set = true;
    }
    retrace_kernel<<<GRID, NTHREADS, SMEM_BYTES>>>(Q, eQ, tQ, r, tp, bp, out);
}